// round 14
// baseline (speedup 1.0000x reference)
#include <cuda_runtime.h>
#include <cuda_bf16.h>
#include <math.h>
#include <stdint.h>

// ---------------------------------------------------------------------------
// HGCN layer. Persistent bf16-split mma.sync GEMM, 64-row tiles, 2 CTAs/SM
// (cross-CTA phase overlap) -> g_ht; CSR build on forked stream;
// gather-aggregate + fused finalize. N=100000, E=600000, D=128.
// ---------------------------------------------------------------------------

#define D 128
#define THREADS 256
#define TM 64                  // tile rows
#define RSTRIDE 272            // bytes per padded bf16 row (128 bf16 + 8 pad)
#define NCAP 100352
#define ECAP 600064

__device__ __align__(16) float g_ht[NCAP * D];

__device__ int  g_cnt[NCAP];            // zeroed by k_scan23 for next call
__device__ int  g_off[NCAP + 1];
__device__ int  g_cur[NCAP];
__device__ int  g_bsum[128];
__device__ __align__(8) int2 g_sw[ECAP];

struct HxStreams {
    cudaStream_t s2;
    cudaEvent_t  eF, eJ;
    HxStreams() {
        cudaStreamCreateWithFlags(&s2, cudaStreamNonBlocking);
        cudaEventCreateWithFlags(&eF, cudaEventDisableTiming);
        cudaEventCreateWithFlags(&eJ, cudaEventDisableTiming);
    }
};
static HxStreams g_hx;

__device__ __forceinline__ float wsum(float v) {
#pragma unroll
    for (int o = 16; o; o >>= 1) v += __shfl_xor_sync(0xffffffffu, v, o);
    return v;
}

__device__ __forceinline__ void mma_bf16(float* c, const uint32_t* a,
                                         const uint32_t* b) {
    asm volatile(
        "mma.sync.aligned.m16n8k16.row.col.f32.bf16.bf16.f32 "
        "{%0,%1,%2,%3}, {%4,%5,%6,%7}, {%8,%9}, {%0,%1,%2,%3};"
        : "+f"(c[0]), "+f"(c[1]), "+f"(c[2]), "+f"(c[3])
        : "r"(a[0]), "r"(a[1]), "r"(a[2]), "r"(a[3]), "r"(b[0]), "r"(b[1]));
}

// dynamic smem layout (bytes): X bufs 64 rows, W bufs 128 rows
#define S_XH 0
#define S_XL (S_XH + TM * RSTRIDE)          // 17408
#define S_WH (S_XL + TM * RSTRIDE)          // 34816
#define S_WL (S_WH + 128 * RSTRIDE)         // 69632
#define S_TOTAL (S_WL + 128 * RSTRIDE)      // 104448 -> 2 CTAs/SM
#define S_OUT 0                              // staging overlay (X region, 33792B)

__device__ __forceinline__ void detect_stride(const int* __restrict__ ei32,
                                              int tid, int* s_st) {
    if (tid < 32) {
        int hi = __ldg(ei32 + 2 * tid + 1) | __ldg(ei32 + 2 * tid + 65);
        unsigned any = __ballot_sync(0xffffffffu, hi != 0);
        if (tid == 0) *s_st = any ? 1 : 2;
    }
    __syncthreads();
}

// ---------------------------------------------------------------------------
// CSR build (identical to the 122us version)
// ---------------------------------------------------------------------------
__global__ void k_count(const int* __restrict__ ei32, int E) {
    __shared__ int s_st;
    detect_stride(ei32, threadIdx.x, &s_st);
    int base = (blockIdx.x * blockDim.x + threadIdx.x) * 4;
    if (base >= E) return;
    int st = s_st;
    const int* dp = ei32 + (size_t)E * st;
    int d0 = __ldg(dp + (size_t)base * st);
    int d1 = (base + 1 < E) ? __ldg(dp + (size_t)(base + 1) * st) : -1;
    int d2 = (base + 2 < E) ? __ldg(dp + (size_t)(base + 2) * st) : -1;
    int d3 = (base + 3 < E) ? __ldg(dp + (size_t)(base + 3) * st) : -1;
    atomicAdd(&g_cnt[d0], 1);
    if (d1 >= 0) atomicAdd(&g_cnt[d1], 1);
    if (d2 >= 0) atomicAdd(&g_cnt[d2], 1);
    if (d3 >= 0) atomicAdd(&g_cnt[d3], 1);
}

__global__ void k_scan1(int Nn) {
    __shared__ int s_w[32], s_ws[32];
    int tidx = threadIdx.x, lane = tidx & 31, wid = tidx >> 5;
    int i = blockIdx.x * 1024 + tidx;
    int c = (i < Nn) ? g_cnt[i] : 0;
    int v = c;
#pragma unroll
    for (int o = 1; o < 32; o <<= 1) {
        int u = __shfl_up_sync(0xffffffffu, v, o);
        if (lane >= o) v += u;
    }
    if (lane == 31) s_w[wid] = v;
    __syncthreads();
    if (wid == 0) {
        int s = s_w[lane];
#pragma unroll
        for (int o = 1; o < 32; o <<= 1) {
            int u = __shfl_up_sync(0xffffffffu, s, o);
            if (lane >= o) s += u;
        }
        s_ws[lane] = s;
    }
    __syncthreads();
    int base = wid ? s_ws[wid - 1] : 0;
    int incl = base + v;
    g_off[i] = incl - c;
    if (tidx == 1023) g_bsum[blockIdx.x] = incl;
}

__global__ void k_scan23(int nb, int Nn) {
    __shared__ int s_b[128];
    int t = threadIdx.x;
    if (t < 128) s_b[t] = (t < nb) ? g_bsum[t] : 0;
    __syncthreads();
    for (int o = 1; o < 128; o <<= 1) {
        int v = 0;
        if (t < 128 && t >= o) v = s_b[t - o];
        __syncthreads();
        if (t < 128) s_b[t] += v;
        __syncthreads();
    }
    int boff = (blockIdx.x == 0) ? 0 : s_b[blockIdx.x - 1];
    int i = blockIdx.x * 1024 + t;
    if (i < Nn) {
        int o = g_off[i] + boff;
        g_off[i] = o;
        g_cur[i] = o;
        g_cnt[i] = 0;
    }
    if (blockIdx.x == 0 && t == 0) g_off[Nn] = s_b[nb - 1];
}

__global__ void k_fill(const int* __restrict__ ei32,
                       const float* __restrict__ ew, int E) {
    __shared__ int s_st;
    detect_stride(ei32, threadIdx.x, &s_st);
    int base = (blockIdx.x * blockDim.x + threadIdx.x) * 4;
    if (base >= E) return;
    int st = s_st;
    const int* sp = ei32;
    const int* dp = ei32 + (size_t)E * st;
    int s0, s1 = 0, s2 = 0, s3 = 0, d0, d1 = -1, d2 = -1, d3 = -1;
    float w0, w1 = 0.f, w2 = 0.f, w3 = 0.f;
    s0 = __ldg(sp + (size_t)base * st);
    d0 = __ldg(dp + (size_t)base * st);
    w0 = __ldg(ew + base);
    if (base + 1 < E) {
        s1 = __ldg(sp + (size_t)(base + 1) * st);
        d1 = __ldg(dp + (size_t)(base + 1) * st);
        w1 = __ldg(ew + base + 1);
    }
    if (base + 2 < E) {
        s2 = __ldg(sp + (size_t)(base + 2) * st);
        d2 = __ldg(dp + (size_t)(base + 2) * st);
        w2 = __ldg(ew + base + 2);
    }
    if (base + 3 < E) {
        s3 = __ldg(sp + (size_t)(base + 3) * st);
        d3 = __ldg(dp + (size_t)(base + 3) * st);
        w3 = __ldg(ew + base + 3);
    }
    g_sw[atomicAdd(&g_cur[d0], 1)] = make_int2(s0, __float_as_int(w0));
    if (d1 >= 0) g_sw[atomicAdd(&g_cur[d1], 1)] = make_int2(s1, __float_as_int(w1));
    if (d2 >= 0) g_sw[atomicAdd(&g_cur[d2], 1)] = make_int2(s2, __float_as_int(w2));
    if (d3 >= 0) g_sw[atomicAdd(&g_cur[d3], 1)] = make_int2(s3, __float_as_int(w3));
}

// ---------------------------------------------------------------------------
// GEMM helpers
// ---------------------------------------------------------------------------
__device__ __forceinline__ void load_split_rows(const float* __restrict__ src,
                                                char* sm, int bh, int bl,
                                                int t, int nrows,
                                                bool do_norm, float* xn2,
                                                int row0, int N) {
    int w = t >> 5, lane = t & 31;     // 8 warps; row r = i*8 + w
    int iters = nrows >> 3;
#pragma unroll 4
    for (int i = 0; i < iters; i++) {
        int r = i * 8 + w;
        float4 v;
        if (do_norm) {
            int g = row0 + r;
            v = (g < N) ? *(const float4*)(src + (size_t)g * D + lane * 4)
                        : make_float4(0.f, 0.f, 0.f, 0.f);
            float s = wsum(v.x * v.x + v.y * v.y + v.z * v.z + v.w * v.w);
            if (lane == 0) xn2[r] = s;
        } else {
            v = *(const float4*)(src + (size_t)r * D + lane * 4);
        }
        __nv_bfloat162 h01 = __floats2bfloat162_rn(v.x, v.y);
        __nv_bfloat162 h23 = __floats2bfloat162_rn(v.z, v.w);
        float2 hf01 = __bfloat1622float2(h01);
        float2 hf23 = __bfloat1622float2(h23);
        __nv_bfloat162 l01 = __floats2bfloat162_rn(v.x - hf01.x, v.y - hf01.y);
        __nv_bfloat162 l23 = __floats2bfloat162_rn(v.z - hf23.x, v.w - hf23.y);
        uint2 hv = make_uint2(*(uint32_t*)&h01, *(uint32_t*)&h23);
        uint2 lv = make_uint2(*(uint32_t*)&l01, *(uint32_t*)&l23);
        int off = r * RSTRIDE + 8 * lane;
        *(uint2*)(sm + bh + off) = hv;
        *(uint2*)(sm + bl + off) = lv;
    }
}

__device__ __forceinline__ float2 mobius_ab(float mxn2, float mp, float xnn2,
                                            float y2) {
    float mxn_raw = sqrtf(mxn2);
    float mxn = fmaxf(mxn_raw, 1e-15f);
    float xn = fmaxf(sqrtf(xnn2), 1e-15f);
    float artx = atanhf(fminf(xn, 1.f - 1e-7f));
    float sc = tanhf(mxn / xn * artx) / mxn;
    if (mxn_raw <= 1e-10f) sc = 0.f;
    float x2 = sc * sc * mxn2;
    float xy = sc * mp;
    float c1 = 1.f + 2.f * xy + y2;
    float c2v = 1.f - x2;
    float den = fmaxf(1.f + 2.f * xy + x2 * y2, 1e-15f);
    float nb2 = (c1 * c1 * x2 + 2.f * c1 * c2v * xy + c2v * c2v * y2) /
                (den * den);
    float nb = fmaxf(sqrtf(nb2), 1e-15f);
    float sl = atanhf(fminf(nb, 1.f - 1e-7f)) / nb;
    return make_float2(sl * c1 * sc / den, sl * c2v / den);
}

// ---------------------------------------------------------------------------
// K1: persistent GEMM, 64-row tiles, 256 threads (8 warps), 2 CTAs/SM.
// Warp = (rowgroup wg<4, half h): rows 16*wg + g4 (+8), N-tiles [8h, 8h+8).
// ---------------------------------------------------------------------------
__global__ void __launch_bounds__(THREADS, 2)
k_linear(const float* __restrict__ x, const float* __restrict__ W,
         const float* __restrict__ b, int N, int ntiles) {
    extern __shared__ char sm[];
    __shared__ float xn2[TM];
    __shared__ float p_s[128];
    __shared__ float red[4];
    __shared__ float s_p2;
    __shared__ float sA[THREADS], sB[THREADS], sC[THREADS], sD[THREADS];

    const int t = threadIdx.x;
    const int w = t >> 5, lane = t & 31;
    const int wg = w >> 1, half = w & 1;
    const int g4 = lane >> 2, tg = lane & 3;

    float bv = 0.f;
    if (t < 128) {
        bv = __ldg(b + t);
        float s = wsum(bv * bv);
        if ((t & 31) == 0) red[t >> 5] = s;
    }
    __syncthreads();
    float bn2 = red[0] + red[1] + red[2] + red[3];
    __syncthreads();
    if (t < 128) {
        float n = fmaxf(sqrtf(bn2), 1e-15f);
        float p = tanhf(n) * bv / n;
        p_s[t] = p;
        float s2 = wsum(p * p);
        if ((t & 31) == 0) red[t >> 5] = s2;
    }
    __syncthreads();
    if (t == 0) s_p2 = red[0] + red[1] + red[2] + red[3];

    load_split_rows(W, sm, S_WH, S_WL, t, 128, false, xn2, 0, N);  // resident

    const char* Xh = sm + S_XH;
    const char* Xl = sm + S_XL;
    const char* Wh = sm + S_WH;
    const char* Wl = sm + S_WL;
    const int ra = (16 * wg + g4) * RSTRIDE;
    const int ka0 = 4 * tg;
    const int r0 = 16 * wg + g4, r1 = r0 + 8;
    const int nt0 = 8 * half;               // first N-tile for this warp

    for (int tile = blockIdx.x; tile < ntiles; tile += gridDim.x) {
        const int row0 = tile * TM;
        load_split_rows(x, sm, S_XH, S_XL, t, TM, true, xn2, row0, N);
        __syncthreads();

        float acc[8][4];
#pragma unroll
        for (int nt = 0; nt < 8; nt++)
#pragma unroll
            for (int j = 0; j < 4; j++) acc[nt][j] = 0.f;

#pragma unroll
        for (int ks = 0; ks < 8; ks++) {
            const int kb = 32 * ks + ka0;
            uint32_t ah[4], al[4];
            ah[0] = *(const uint32_t*)(Xh + ra + kb);
            ah[1] = *(const uint32_t*)(Xh + ra + 8 * RSTRIDE + kb);
            ah[2] = *(const uint32_t*)(Xh + ra + kb + 16);
            ah[3] = *(const uint32_t*)(Xh + ra + 8 * RSTRIDE + kb + 16);
            al[0] = *(const uint32_t*)(Xl + ra + kb);
            al[1] = *(const uint32_t*)(Xl + ra + 8 * RSTRIDE + kb);
            al[2] = *(const uint32_t*)(Xl + ra + kb + 16);
            al[3] = *(const uint32_t*)(Xl + ra + 8 * RSTRIDE + kb + 16);
#pragma unroll
            for (int nt = 0; nt < 8; nt++) {
                const int rb = (8 * (nt0 + nt) + g4) * RSTRIDE;
                uint32_t bh[2], bl[2];
                bh[0] = *(const uint32_t*)(Wh + rb + kb);
                bh[1] = *(const uint32_t*)(Wh + rb + kb + 16);
                bl[0] = *(const uint32_t*)(Wl + rb + kb);
                bl[1] = *(const uint32_t*)(Wl + rb + kb + 16);
                mma_bf16(acc[nt], ah, bh);
                mma_bf16(acc[nt], ah, bl);
                mma_bf16(acc[nt], al, bh);
            }
        }

        // partial epilogue sums over this warp's 8 N-tiles (16 cols/row)
        float n2a = 0.f, mpa = 0.f, n2b = 0.f, mpb = 0.f;
#pragma unroll
        for (int nt = 0; nt < 8; nt++) {
            int c = 8 * (nt0 + nt) + 2 * tg;
            float p0 = p_s[c], p1 = p_s[c + 1];
            n2a = fmaf(acc[nt][0], acc[nt][0], fmaf(acc[nt][1], acc[nt][1], n2a));
            mpa = fmaf(acc[nt][0], p0, fmaf(acc[nt][1], p1, mpa));
            n2b = fmaf(acc[nt][2], acc[nt][2], fmaf(acc[nt][3], acc[nt][3], n2b));
            mpb = fmaf(acc[nt][2], p0, fmaf(acc[nt][3], p1, mpb));
        }
        n2a += __shfl_xor_sync(0xffffffffu, n2a, 1);
        n2a += __shfl_xor_sync(0xffffffffu, n2a, 2);
        mpa += __shfl_xor_sync(0xffffffffu, mpa, 1);
        mpa += __shfl_xor_sync(0xffffffffu, mpa, 2);
        n2b += __shfl_xor_sync(0xffffffffu, n2b, 1);
        n2b += __shfl_xor_sync(0xffffffffu, n2b, 2);
        mpb += __shfl_xor_sync(0xffffffffu, mpb, 1);
        mpb += __shfl_xor_sync(0xffffffffu, mpb, 2);

        // cross-half combine (t ^ 32 = same wg/lane, other half)
        sA[t] = n2a; sB[t] = mpa; sC[t] = n2b; sD[t] = mpb;
        __syncthreads();
        n2a = sA[t] + sA[t ^ 32];
        mpa = sB[t] + sB[t ^ 32];
        n2b = sC[t] + sC[t ^ 32];
        mpb = sD[t] + sD[t ^ 32];

        const float y2 = s_p2;
        float2 ab0 = mobius_ab(n2a, mpa, xn2[r0], y2);
        float2 ab1 = mobius_ab(n2b, mpb, xn2[r1], y2);
        __syncthreads();   // sA..sD read done; X region about to be staged

        float* stg = (float*)(sm + S_OUT);     // [64][132] f32 = 33792 B
#pragma unroll
        for (int nt = 0; nt < 8; nt++) {
            int c = 8 * (nt0 + nt) + 2 * tg;
            float p0 = p_s[c], p1 = p_s[c + 1];
            *(float2*)&stg[r0 * 132 + c] = make_float2(
                fmaf(ab0.x, acc[nt][0], ab0.y * p0),
                fmaf(ab0.x, acc[nt][1], ab0.y * p1));
            *(float2*)&stg[r1 * 132 + c] = make_float2(
                fmaf(ab1.x, acc[nt][2], ab1.y * p0),
                fmaf(ab1.x, acc[nt][3], ab1.y * p1));
        }
        __syncthreads();

        // coalesced flush: 64 rows x 32 float4
#pragma unroll 2
        for (int idx = t; idx < TM * 32; idx += THREADS) {
            int r2 = idx >> 5, c4 = idx & 31;
            int g = row0 + r2;
            if (g < N)
                *(float4*)&g_ht[(size_t)g * D + c4 * 4] =
                    *(const float4*)&stg[r2 * 132 + c4 * 4];
        }
        __syncthreads();
    }
}

// ---------------------------------------------------------------------------
// K_agg: one warp per dst; batched meta prefetch + 4-way independent fp32
// gathers; fused finalize. (identical to the 122us version)
// ---------------------------------------------------------------------------
__global__ void __launch_bounds__(256)
k_agg(float* __restrict__ out, const float* __restrict__ a_ptr, int N) {
    int gw = (int)((blockIdx.x * blockDim.x + threadIdx.x) >> 5);
    if (gw >= N) return;
    int lane = threadIdx.x & 31;
    float a = __ldg(a_ptr);

    int beg = g_off[gw], end = g_off[gw + 1];
    int deg = end - beg;
    float4 acc = __ldg((const float4*)(g_ht + (size_t)gw * D) + lane);

    for (int base = 0; base < deg; base += 32) {
        int m = deg - base; if (m > 32) m = 32;
        int2 meta = make_int2(0, 0);
        if (lane < m) meta = __ldg(&g_sw[beg + base + lane]);
        for (int j = 0; j < m; j += 4) {
            int s0 = __shfl_sync(0xffffffffu, meta.x, j);
            int s1 = __shfl_sync(0xffffffffu, meta.x, j + 1);
            int s2 = __shfl_sync(0xffffffffu, meta.x, j + 2);
            int s3 = __shfl_sync(0xffffffffu, meta.x, j + 3);
            float w0 = __int_as_float(__shfl_sync(0xffffffffu, meta.y, j));
            float w1 = __int_as_float(__shfl_sync(0xffffffffu, meta.y, j + 1));
            float w2 = __int_as_float(__shfl_sync(0xffffffffu, meta.y, j + 2));
            float w3 = __int_as_float(__shfl_sync(0xffffffffu, meta.y, j + 3));
            float4 v0 = __ldg((const float4*)(g_ht + (size_t)s0 * D) + lane);
            float4 v1 = __ldg((const float4*)(g_ht + (size_t)s1 * D) + lane);
            float4 v2 = __ldg((const float4*)(g_ht + (size_t)s2 * D) + lane);
            float4 v3 = __ldg((const float4*)(g_ht + (size_t)s3 * D) + lane);
            acc.x = fmaf(w0, v0.x, fmaf(w1, v1.x, fmaf(w2, v2.x, fmaf(w3, v3.x, acc.x))));
            acc.y = fmaf(w0, v0.y, fmaf(w1, v1.y, fmaf(w2, v2.y, fmaf(w3, v3.y, acc.y))));
            acc.z = fmaf(w0, v0.z, fmaf(w1, v1.z, fmaf(w2, v2.z, fmaf(w3, v3.z, acc.z))));
            acc.w = fmaf(w0, v0.w, fmaf(w1, v1.w, fmaf(w2, v2.w, fmaf(w3, v3.w, acc.w))));
        }
    }

    float n1 = fmaxf(sqrtf(wsum(acc.x * acc.x + acc.y * acc.y +
                                acc.z * acc.z + acc.w * acc.w)), 1e-15f);
    float s = atanhf(fminf(tanhf(n1), 1.f - 1e-7f)) / n1;
    float tx = acc.x * s, ty = acc.y * s, tz = acc.z * s, tw = acc.w * s;
    tx = tx >= 0.f ? tx : a * tx;
    ty = ty >= 0.f ? ty : a * ty;
    tz = tz >= 0.f ? tz : a * tz;
    tw = tw >= 0.f ? tw : a * tw;
    float n3 = fmaxf(sqrtf(wsum(tx * tx + ty * ty + tz * tz + tw * tw)), 1e-15f);
    float th = tanhf(n3);
    float s2 = th / n3;
    float ox = tx * s2, oy = ty * s2, oz = tz * s2, ow = tw * s2;
    float n4 = fmaxf(th, 1e-15f);
    const float maxn = 1.f - 4e-3f;
    if (n4 > maxn) {
        float f = maxn / n4;
        ox *= f; oy *= f; oz *= f; ow *= f;
    }
    *((float4*)(out + (size_t)gw * D) + lane) = make_float4(ox, oy, oz, ow);
}

// ---------------------------------------------------------------------------
extern "C" void kernel_launch(void* const* d_in, const int* in_sizes, int n_in,
                              void* d_out, int out_size) {
    const float* x    = (const float*)d_in[0];
    const int*   ei32 = (const int*)d_in[1];
    const float* ew   = (const float*)d_in[2];
    const float* W    = (const float*)d_in[3];
    const float* b    = (const float*)d_in[4];
    const float* a    = (const float*)d_in[5];
    float* out = (float*)d_out;

    int N = in_sizes[0] / D;
    int E = in_sizes[2];
    int nb = (N + 1023) / 1024;
    int ntiles = (N + TM - 1) / TM;
    int e4 = (E + 1023) / 1024;

    // fork: CSR build on side stream, concurrent with k_linear
    cudaEventRecord(g_hx.eF, 0);
    cudaStreamWaitEvent(g_hx.s2, g_hx.eF, 0);
    k_count<<<e4, 256, 0, g_hx.s2>>>(ei32, E);
    k_scan1<<<nb, 1024, 0, g_hx.s2>>>(N);
    k_scan23<<<nb, 1024, 0, g_hx.s2>>>(nb, N);
    k_fill<<<e4, 256, 0, g_hx.s2>>>(ei32, ew, E);
    cudaEventRecord(g_hx.eJ, g_hx.s2);

    cudaFuncSetAttribute(k_linear, cudaFuncAttributeMaxDynamicSharedMemorySize,
                         S_TOTAL);
    int grid = ntiles < 296 ? ntiles : 296;   // 2 CTAs/SM x 148 SMs
    k_linear<<<grid, THREADS, S_TOTAL>>>(x, W, b, N, ntiles);

    cudaStreamWaitEvent(0, g_hx.eJ, 0);
    k_agg<<<(N * 32 + 255) / 256, 256>>>(out, a, N);
}

// round 16
// speedup vs baseline: 1.0509x; 1.0509x over previous
#include <cuda_runtime.h>
#include <cuda_bf16.h>
#include <math.h>
#include <stdint.h>

// ---------------------------------------------------------------------------
// HGCN layer. Persistent bf16-split mma.sync GEMM (512 thr/CTA, W resident,
// ldmatrix-based mainloop) -> g_ht; CSR build on forked stream;
// gather-aggregate + fused finalize. N=100000, E=600000, D=128.
// ---------------------------------------------------------------------------

#define D 128
#define THREADS 512
#define RSTRIDE 272            // bytes per padded bf16 row (128 bf16 + 8 pad)
#define NCAP 100352
#define ECAP 600064

__device__ __align__(16) float g_ht[NCAP * D];

__device__ int  g_cnt[NCAP];            // zeroed by k_scan23 for next call
__device__ int  g_off[NCAP + 1];
__device__ int  g_cur[NCAP];
__device__ int  g_bsum[128];
__device__ __align__(8) int2 g_sw[ECAP];

struct HxStreams {
    cudaStream_t s2;
    cudaEvent_t  eF, eJ;
    HxStreams() {
        cudaStreamCreateWithFlags(&s2, cudaStreamNonBlocking);
        cudaEventCreateWithFlags(&eF, cudaEventDisableTiming);
        cudaEventCreateWithFlags(&eJ, cudaEventDisableTiming);
    }
};
static HxStreams g_hx;

__device__ __forceinline__ float wsum(float v) {
#pragma unroll
    for (int o = 16; o; o >>= 1) v += __shfl_xor_sync(0xffffffffu, v, o);
    return v;
}

__device__ __forceinline__ uint32_t smem_u32(const void* p) {
    uint32_t a;
    asm("{ .reg .u64 t; cvta.to.shared.u64 t, %1; cvt.u32.u64 %0, t; }"
        : "=r"(a) : "l"(p));
    return a;
}

__device__ __forceinline__ void mma_bf16(float* c, const uint32_t* a,
                                         const uint32_t* b) {
    asm volatile(
        "mma.sync.aligned.m16n8k16.row.col.f32.bf16.bf16.f32 "
        "{%0,%1,%2,%3}, {%4,%5,%6,%7}, {%8,%9}, {%0,%1,%2,%3};"
        : "+f"(c[0]), "+f"(c[1]), "+f"(c[2]), "+f"(c[3])
        : "r"(a[0]), "r"(a[1]), "r"(a[2]), "r"(a[3]), "r"(b[0]), "r"(b[1]));
}

#define LDSM4(r, addr)                                                        \
    asm volatile("ldmatrix.sync.aligned.m8n8.x4.shared.b16 "                  \
                 "{%0,%1,%2,%3}, [%4];"                                       \
                 : "=r"((r)[0]), "=r"((r)[1]), "=r"((r)[2]), "=r"((r)[3])     \
                 : "r"(addr))

#define S_XH 0
#define S_XL (S_XH + 128 * RSTRIDE)
#define S_WH (S_XL + 128 * RSTRIDE)
#define S_WL (S_WH + 128 * RSTRIDE)
#define S_TOTAL (S_WL + 128 * RSTRIDE)  // 139264
#define S_OUT 0

__device__ __forceinline__ void detect_stride(const int* __restrict__ ei32,
                                              int tid, int* s_st) {
    if (tid < 32) {
        int hi = __ldg(ei32 + 2 * tid + 1) | __ldg(ei32 + 2 * tid + 65);
        unsigned any = __ballot_sync(0xffffffffu, hi != 0);
        if (tid == 0) *s_st = any ? 1 : 2;
    }
    __syncthreads();
}

// ---------------------------------------------------------------------------
// CSR build (identical to the 122us version)
// ---------------------------------------------------------------------------
__global__ void k_count(const int* __restrict__ ei32, int E) {
    __shared__ int s_st;
    detect_stride(ei32, threadIdx.x, &s_st);
    int base = (blockIdx.x * blockDim.x + threadIdx.x) * 4;
    if (base >= E) return;
    int st = s_st;
    const int* dp = ei32 + (size_t)E * st;
    int d0 = __ldg(dp + (size_t)base * st);
    int d1 = (base + 1 < E) ? __ldg(dp + (size_t)(base + 1) * st) : -1;
    int d2 = (base + 2 < E) ? __ldg(dp + (size_t)(base + 2) * st) : -1;
    int d3 = (base + 3 < E) ? __ldg(dp + (size_t)(base + 3) * st) : -1;
    atomicAdd(&g_cnt[d0], 1);
    if (d1 >= 0) atomicAdd(&g_cnt[d1], 1);
    if (d2 >= 0) atomicAdd(&g_cnt[d2], 1);
    if (d3 >= 0) atomicAdd(&g_cnt[d3], 1);
}

__global__ void k_scan1(int Nn) {
    __shared__ int s_w[32], s_ws[32];
    int tidx = threadIdx.x, lane = tidx & 31, wid = tidx >> 5;
    int i = blockIdx.x * 1024 + tidx;
    int c = (i < Nn) ? g_cnt[i] : 0;
    int v = c;
#pragma unroll
    for (int o = 1; o < 32; o <<= 1) {
        int u = __shfl_up_sync(0xffffffffu, v, o);
        if (lane >= o) v += u;
    }
    if (lane == 31) s_w[wid] = v;
    __syncthreads();
    if (wid == 0) {
        int s = s_w[lane];
#pragma unroll
        for (int o = 1; o < 32; o <<= 1) {
            int u = __shfl_up_sync(0xffffffffu, s, o);
            if (lane >= o) s += u;
        }
        s_ws[lane] = s;
    }
    __syncthreads();
    int base = wid ? s_ws[wid - 1] : 0;
    int incl = base + v;
    g_off[i] = incl - c;
    if (tidx == 1023) g_bsum[blockIdx.x] = incl;
}

__global__ void k_scan23(int nb, int Nn) {
    __shared__ int s_b[128];
    int t = threadIdx.x;
    if (t < 128) s_b[t] = (t < nb) ? g_bsum[t] : 0;
    __syncthreads();
    for (int o = 1; o < 128; o <<= 1) {
        int v = 0;
        if (t < 128 && t >= o) v = s_b[t - o];
        __syncthreads();
        if (t < 128) s_b[t] += v;
        __syncthreads();
    }
    int boff = (blockIdx.x == 0) ? 0 : s_b[blockIdx.x - 1];
    int i = blockIdx.x * 1024 + t;
    if (i < Nn) {
        int o = g_off[i] + boff;
        g_off[i] = o;
        g_cur[i] = o;
        g_cnt[i] = 0;
    }
    if (blockIdx.x == 0 && t == 0) g_off[Nn] = s_b[nb - 1];
}

__global__ void k_fill(const int* __restrict__ ei32,
                       const float* __restrict__ ew, int E) {
    __shared__ int s_st;
    detect_stride(ei32, threadIdx.x, &s_st);
    int base = (blockIdx.x * blockDim.x + threadIdx.x) * 4;
    if (base >= E) return;
    int st = s_st;
    const int* sp = ei32;
    const int* dp = ei32 + (size_t)E * st;
    int s0, s1 = 0, s2 = 0, s3 = 0, d0, d1 = -1, d2 = -1, d3 = -1;
    float w0, w1 = 0.f, w2 = 0.f, w3 = 0.f;
    s0 = __ldg(sp + (size_t)base * st);
    d0 = __ldg(dp + (size_t)base * st);
    w0 = __ldg(ew + base);
    if (base + 1 < E) {
        s1 = __ldg(sp + (size_t)(base + 1) * st);
        d1 = __ldg(dp + (size_t)(base + 1) * st);
        w1 = __ldg(ew + base + 1);
    }
    if (base + 2 < E) {
        s2 = __ldg(sp + (size_t)(base + 2) * st);
        d2 = __ldg(dp + (size_t)(base + 2) * st);
        w2 = __ldg(ew + base + 2);
    }
    if (base + 3 < E) {
        s3 = __ldg(sp + (size_t)(base + 3) * st);
        d3 = __ldg(dp + (size_t)(base + 3) * st);
        w3 = __ldg(ew + base + 3);
    }
    g_sw[atomicAdd(&g_cur[d0], 1)] = make_int2(s0, __float_as_int(w0));
    if (d1 >= 0) g_sw[atomicAdd(&g_cur[d1], 1)] = make_int2(s1, __float_as_int(w1));
    if (d2 >= 0) g_sw[atomicAdd(&g_cur[d2], 1)] = make_int2(s2, __float_as_int(w2));
    if (d3 >= 0) g_sw[atomicAdd(&g_cur[d3], 1)] = make_int2(s3, __float_as_int(w3));
}

// ---------------------------------------------------------------------------
// GEMM helpers
// ---------------------------------------------------------------------------
__device__ __forceinline__ void load_split(const float* __restrict__ src,
                                           char* sm, int bh, int bl,
                                           int t, bool do_norm, float* xn2,
                                           int row0, int N) {
    int w = t >> 5, lane = t & 31;     // 16 warps: rows i*16 + w
#pragma unroll 4
    for (int i = 0; i < 8; i++) {
        int r = i * 16 + w;
        float4 v;
        if (do_norm) {
            int g = row0 + r;
            v = (g < N) ? *(const float4*)(src + (size_t)g * D + lane * 4)
                        : make_float4(0.f, 0.f, 0.f, 0.f);
            float s = wsum(v.x * v.x + v.y * v.y + v.z * v.z + v.w * v.w);
            if (lane == 0) xn2[r] = s;
        } else {
            v = *(const float4*)(src + (size_t)r * D + lane * 4);
        }
        __nv_bfloat162 h01 = __floats2bfloat162_rn(v.x, v.y);
        __nv_bfloat162 h23 = __floats2bfloat162_rn(v.z, v.w);
        float2 hf01 = __bfloat1622float2(h01);
        float2 hf23 = __bfloat1622float2(h23);
        __nv_bfloat162 l01 = __floats2bfloat162_rn(v.x - hf01.x, v.y - hf01.y);
        __nv_bfloat162 l23 = __floats2bfloat162_rn(v.z - hf23.x, v.w - hf23.y);
        uint2 hv = make_uint2(*(uint32_t*)&h01, *(uint32_t*)&h23);
        uint2 lv = make_uint2(*(uint32_t*)&l01, *(uint32_t*)&l23);
        int off = r * RSTRIDE + 8 * lane;
        *(uint2*)(sm + bh + off) = hv;
        *(uint2*)(sm + bl + off) = lv;
    }
}

__device__ __forceinline__ float2 mobius_ab(float mxn2, float mp, float xnn2,
                                            float y2) {
    float mxn_raw = sqrtf(mxn2);
    float mxn = fmaxf(mxn_raw, 1e-15f);
    float xn = fmaxf(sqrtf(xnn2), 1e-15f);
    float artx = atanhf(fminf(xn, 1.f - 1e-7f));
    float sc = tanhf(mxn / xn * artx) / mxn;
    if (mxn_raw <= 1e-10f) sc = 0.f;
    float x2 = sc * sc * mxn2;
    float xy = sc * mp;
    float c1 = 1.f + 2.f * xy + y2;
    float c2v = 1.f - x2;
    float den = fmaxf(1.f + 2.f * xy + x2 * y2, 1e-15f);
    float nb2 = (c1 * c1 * x2 + 2.f * c1 * c2v * xy + c2v * c2v * y2) /
                (den * den);
    float nb = fmaxf(sqrtf(nb2), 1e-15f);
    float sl = atanhf(fminf(nb, 1.f - 1e-7f)) / nb;
    return make_float2(sl * c1 * sc / den, sl * c2v / den);
}

// ---------------------------------------------------------------------------
// K1: persistent GEMM, 512 threads (16 warps), ldmatrix mainloop.
// Warp = (rowgroup wg, half h): rows 16*wg + g4 (+8), N-tiles [8h, 8h+8).
// ---------------------------------------------------------------------------
__global__ void __launch_bounds__(THREADS, 1)
k_linear(const float* __restrict__ x, const float* __restrict__ W,
         const float* __restrict__ b, int N, int ntiles) {
    extern __shared__ char sm[];
    __shared__ float xn2[128];
    __shared__ float p_s[128];
    __shared__ float red[4];
    __shared__ float s_p2;
    __shared__ float sA[THREADS], sB[THREADS], sC[THREADS], sD[THREADS];

    const int t = threadIdx.x;
    const int w = t >> 5, lane = t & 31;
    const int wg = w >> 1, half = w & 1;
    const int g4 = lane >> 2, tg = lane & 3;

    float bv = 0.f;
    if (t < 128) {
        bv = __ldg(b + t);
        float s = wsum(bv * bv);
        if ((t & 31) == 0) red[t >> 5] = s;
    }
    __syncthreads();
    float bn2 = red[0] + red[1] + red[2] + red[3];
    __syncthreads();
    if (t < 128) {
        float n = fmaxf(sqrtf(bn2), 1e-15f);
        float p = tanhf(n) * bv / n;
        p_s[t] = p;
        float s2 = wsum(p * p);
        if ((t & 31) == 0) red[t >> 5] = s2;
    }
    __syncthreads();
    if (t == 0) s_p2 = red[0] + red[1] + red[2] + red[3];

    load_split(W, sm, S_WH, S_WL, t, false, xn2, 0, N);   // resident

    const int r0 = 16 * wg + g4, r1 = r0 + 8;
    const int nt0 = 8 * half;               // first N-tile for this warp

    // per-lane ldmatrix base addresses (computed once)
    const uint32_t smb = smem_u32(sm);
    // A x4: lanes 0-15 -> rows 16wg+(L&15) klo; lanes 16-31 -> same rows khi
    const uint32_t aoff = (uint32_t)((16 * wg + (lane & 15)) * RSTRIDE +
                                     (lane >> 4) * 16);
    const uint32_t aH = smb + S_XH + aoff;
    const uint32_t aL = smb + S_XL + aoff;
    // B x4 per nt-pair p: f0,f1 = (nt=nt0+2p) klo/khi; f2,f3 = (nt+1) klo/khi
    // lanes 0-7: rows 8nt+(L&7) +0 | 8-15: +16 | 16-23: rows+8 +0 | 24-31: +16
    uint32_t bH[4], bL[4];
#pragma unroll
    for (int p = 0; p < 4; p++) {
        uint32_t boff = (uint32_t)((8 * (nt0 + 2 * p) + (lane & 7) +
                                    (lane >> 4) * 8) * RSTRIDE +
                                   ((lane >> 3) & 1) * 16);
        bH[p] = smb + S_WH + boff;
        bL[p] = smb + S_WL + boff;
    }

    for (int tile = blockIdx.x; tile < ntiles; tile += gridDim.x) {
        const int row0 = tile * 128;
        load_split(x, sm, S_XH, S_XL, t, true, xn2, row0, N);
        __syncthreads();

        float acc[8][4];
#pragma unroll
        for (int nt = 0; nt < 8; nt++)
#pragma unroll
            for (int j = 0; j < 4; j++) acc[nt][j] = 0.f;

#pragma unroll
        for (int ks = 0; ks < 8; ks++) {
            const uint32_t ko = 32u * ks;
            uint32_t ah[4], al[4];
            LDSM4(ah, aH + ko);
            LDSM4(al, aL + ko);
#pragma unroll
            for (int p = 0; p < 4; p++) {
                uint32_t bh[4], bl[4];
                LDSM4(bh, bH[p] + ko);
                LDSM4(bl, bL[p] + ko);
                mma_bf16(acc[2 * p],     ah, bh);
                mma_bf16(acc[2 * p],     ah, bl);
                mma_bf16(acc[2 * p],     al, bh);
                mma_bf16(acc[2 * p + 1], ah, bh + 2);
                mma_bf16(acc[2 * p + 1], ah, bl + 2);
                mma_bf16(acc[2 * p + 1], al, bh + 2);
            }
        }

        // partial epilogue sums over this warp's 8 N-tiles (16 cols/row)
        float n2a = 0.f, mpa = 0.f, n2b = 0.f, mpb = 0.f;
#pragma unroll
        for (int nt = 0; nt < 8; nt++) {
            float p0 = p_s[8 * (nt0 + nt) + 2 * tg];
            float p1 = p_s[8 * (nt0 + nt) + 2 * tg + 1];
            n2a = fmaf(acc[nt][0], acc[nt][0], fmaf(acc[nt][1], acc[nt][1], n2a));
            mpa = fmaf(acc[nt][0], p0, fmaf(acc[nt][1], p1, mpa));
            n2b = fmaf(acc[nt][2], acc[nt][2], fmaf(acc[nt][3], acc[nt][3], n2b));
            mpb = fmaf(acc[nt][2], p0, fmaf(acc[nt][3], p1, mpb));
        }
        n2a += __shfl_xor_sync(0xffffffffu, n2a, 1);
        n2a += __shfl_xor_sync(0xffffffffu, n2a, 2);
        mpa += __shfl_xor_sync(0xffffffffu, mpa, 1);
        mpa += __shfl_xor_sync(0xffffffffu, mpa, 2);
        n2b += __shfl_xor_sync(0xffffffffu, n2b, 1);
        n2b += __shfl_xor_sync(0xffffffffu, n2b, 2);
        mpb += __shfl_xor_sync(0xffffffffu, mpb, 1);
        mpb += __shfl_xor_sync(0xffffffffu, mpb, 2);

        // cross-half combine (t ^ 32 = same wg/lane, other half)
        sA[t] = n2a; sB[t] = mpa; sC[t] = n2b; sD[t] = mpb;
        __syncthreads();
        n2a = sA[t] + sA[t ^ 32];
        mpa = sB[t] + sB[t ^ 32];
        n2b = sC[t] + sC[t ^ 32];
        mpb = sD[t] + sD[t ^ 32];

        const float y2 = s_p2;
        float2 ab0 = mobius_ab(n2a, mpa, xn2[r0], y2);
        float2 ab1 = mobius_ab(n2b, mpb, xn2[r1], y2);
        __syncthreads();   // sA..sD reads done; X region about to be staged

        float* stg = (float*)(sm + S_OUT);
#pragma unroll
        for (int nt = 0; nt < 8; nt++) {
            int c = 8 * (nt0 + nt) + 2 * tg;
            float p0 = p_s[c], p1 = p_s[c + 1];
            *(float2*)&stg[r0 * 132 + c] = make_float2(
                fmaf(ab0.x, acc[nt][0], ab0.y * p0),
                fmaf(ab0.x, acc[nt][1], ab0.y * p1));
            *(float2*)&stg[r1 * 132 + c] = make_float2(
                fmaf(ab1.x, acc[nt][2], ab1.y * p0),
                fmaf(ab1.x, acc[nt][3], ab1.y * p1));
        }
        __syncthreads();

#pragma unroll 2
        for (int idx = t; idx < 128 * 32; idx += THREADS) {
            int r2 = idx >> 5, c4 = idx & 31;
            int g = row0 + r2;
            if (g < N)
                *(float4*)&g_ht[(size_t)g * D + c4 * 4] =
                    *(const float4*)&stg[r2 * 132 + c4 * 4];
        }
        __syncthreads();
    }
}

// ---------------------------------------------------------------------------
// K_agg: one warp per dst; batched meta prefetch + 4-way independent fp32
// gathers; fused finalize.  (identical to the 122us version)
// ---------------------------------------------------------------------------
__global__ void __launch_bounds__(256)
k_agg(float* __restrict__ out, const float* __restrict__ a_ptr, int N) {
    int gw = (int)((blockIdx.x * blockDim.x + threadIdx.x) >> 5);
    if (gw >= N) return;
    int lane = threadIdx.x & 31;
    float a = __ldg(a_ptr);

    int beg = g_off[gw], end = g_off[gw + 1];
    int deg = end - beg;
    float4 acc = __ldg((const float4*)(g_ht + (size_t)gw * D) + lane);

    for (int base = 0; base < deg; base += 32) {
        int m = deg - base; if (m > 32) m = 32;
        int2 meta = make_int2(0, 0);
        if (lane < m) meta = __ldg(&g_sw[beg + base + lane]);
        for (int j = 0; j < m; j += 4) {
            int s0 = __shfl_sync(0xffffffffu, meta.x, j);
            int s1 = __shfl_sync(0xffffffffu, meta.x, j + 1);
            int s2 = __shfl_sync(0xffffffffu, meta.x, j + 2);
            int s3 = __shfl_sync(0xffffffffu, meta.x, j + 3);
            float w0 = __int_as_float(__shfl_sync(0xffffffffu, meta.y, j));
            float w1 = __int_as_float(__shfl_sync(0xffffffffu, meta.y, j + 1));
            float w2 = __int_as_float(__shfl_sync(0xffffffffu, meta.y, j + 2));
            float w3 = __int_as_float(__shfl_sync(0xffffffffu, meta.y, j + 3));
            float4 v0 = __ldg((const float4*)(g_ht + (size_t)s0 * D) + lane);
            float4 v1 = __ldg((const float4*)(g_ht + (size_t)s1 * D) + lane);
            float4 v2 = __ldg((const float4*)(g_ht + (size_t)s2 * D) + lane);
            float4 v3 = __ldg((const float4*)(g_ht + (size_t)s3 * D) + lane);
            acc.x = fmaf(w0, v0.x, fmaf(w1, v1.x, fmaf(w2, v2.x, fmaf(w3, v3.x, acc.x))));
            acc.y = fmaf(w0, v0.y, fmaf(w1, v1.y, fmaf(w2, v2.y, fmaf(w3, v3.y, acc.y))));
            acc.z = fmaf(w0, v0.z, fmaf(w1, v1.z, fmaf(w2, v2.z, fmaf(w3, v3.z, acc.z))));
            acc.w = fmaf(w0, v0.w, fmaf(w1, v1.w, fmaf(w2, v2.w, fmaf(w3, v3.w, acc.w))));
        }
    }

    float n1 = fmaxf(sqrtf(wsum(acc.x * acc.x + acc.y * acc.y +
                                acc.z * acc.z + acc.w * acc.w)), 1e-15f);
    float s = atanhf(fminf(tanhf(n1), 1.f - 1e-7f)) / n1;
    float tx = acc.x * s, ty = acc.y * s, tz = acc.z * s, tw = acc.w * s;
    tx = tx >= 0.f ? tx : a * tx;
    ty = ty >= 0.f ? ty : a * ty;
    tz = tz >= 0.f ? tz : a * tz;
    tw = tw >= 0.f ? tw : a * tw;
    float n3 = fmaxf(sqrtf(wsum(tx * tx + ty * ty + tz * tz + tw * tw)), 1e-15f);
    float th = tanhf(n3);
    float s2 = th / n3;
    float ox = tx * s2, oy = ty * s2, oz = tz * s2, ow = tw * s2;
    float n4 = fmaxf(th, 1e-15f);
    const float maxn = 1.f - 4e-3f;
    if (n4 > maxn) {
        float f = maxn / n4;
        ox *= f; oy *= f; oz *= f; ow *= f;
    }
    *((float4*)(out + (size_t)gw * D) + lane) = make_float4(ox, oy, oz, ow);
}

// ---------------------------------------------------------------------------
extern "C" void kernel_launch(void* const* d_in, const int* in_sizes, int n_in,
                              void* d_out, int out_size) {
    const float* x    = (const float*)d_in[0];
    const int*   ei32 = (const int*)d_in[1];
    const float* ew   = (const float*)d_in[2];
    const float* W    = (const float*)d_in[3];
    const float* b    = (const float*)d_in[4];
    const float* a    = (const float*)d_in[5];
    float* out = (float*)d_out;

    int N = in_sizes[0] / D;
    int E = in_sizes[2];
    int nb = (N + 1023) / 1024;
    int ntiles = (N + 127) / 128;
    int e4 = (E + 1023) / 1024;

    // fork: CSR build on side stream, concurrent with k_linear
    cudaEventRecord(g_hx.eF, 0);
    cudaStreamWaitEvent(g_hx.s2, g_hx.eF, 0);
    k_count<<<e4, 256, 0, g_hx.s2>>>(ei32, E);
    k_scan1<<<nb, 1024, 0, g_hx.s2>>>(N);
    k_scan23<<<nb, 1024, 0, g_hx.s2>>>(nb, N);
    k_fill<<<e4, 256, 0, g_hx.s2>>>(ei32, ew, E);
    cudaEventRecord(g_hx.eJ, g_hx.s2);

    cudaFuncSetAttribute(k_linear, cudaFuncAttributeMaxDynamicSharedMemorySize,
                         S_TOTAL);
    int grid = ntiles < 148 ? ntiles : 148;
    k_linear<<<grid, THREADS, S_TOTAL>>>(x, W, b, N, ntiles);

    cudaStreamWaitEvent(0, g_hx.eJ, 0);
    k_agg<<<(N * 32 + 255) / 256, 256>>>(out, a, N);
}

// round 17
// speedup vs baseline: 1.0706x; 1.0187x over previous
#include <cuda_runtime.h>
#include <cuda_bf16.h>
#include <cuda_fp16.h>
#include <math.h>
#include <stdint.h>

// ---------------------------------------------------------------------------
// HGCN layer. Persistent bf16-split mma.sync GEMM (512 thr/CTA, W resident,
// ldmatrix mainloop) -> g_ht (fp32) + g_hth (fp16 gather mirror); CSR build
// on forked stream; gather-aggregate (fp16 payload, fp32 self/weights) +
// fused finalize. N=100000, E=600000, D=128.
// ---------------------------------------------------------------------------

#define D 128
#define THREADS 512
#define RSTRIDE 272            // bytes per padded bf16 row (128 bf16 + 8 pad)
#define NCAP 100352
#define ECAP 600064

__device__ __align__(16) float  g_ht[NCAP * D];     // fp32 (self term)
__device__ __align__(16) __half g_hth[NCAP * D];    // fp16 (gather payload)

__device__ int  g_cnt[NCAP];            // zeroed by k_scan23 for next call
__device__ int  g_off[NCAP + 1];
__device__ int  g_cur[NCAP];
__device__ int  g_bsum[128];
__device__ __align__(8) int2 g_sw[ECAP];

struct HxStreams {
    cudaStream_t s2;
    cudaEvent_t  eF, eJ;
    HxStreams() {
        cudaStreamCreateWithFlags(&s2, cudaStreamNonBlocking);
        cudaEventCreateWithFlags(&eF, cudaEventDisableTiming);
        cudaEventCreateWithFlags(&eJ, cudaEventDisableTiming);
    }
};
static HxStreams g_hx;

__device__ __forceinline__ float wsum(float v) {
#pragma unroll
    for (int o = 16; o; o >>= 1) v += __shfl_xor_sync(0xffffffffu, v, o);
    return v;
}

__device__ __forceinline__ uint32_t smem_u32(const void* p) {
    uint32_t a;
    asm("{ .reg .u64 t; cvta.to.shared.u64 t, %1; cvt.u32.u64 %0, t; }"
        : "=r"(a) : "l"(p));
    return a;
}

__device__ __forceinline__ void mma_bf16(float* c, const uint32_t* a,
                                         const uint32_t* b) {
    asm volatile(
        "mma.sync.aligned.m16n8k16.row.col.f32.bf16.bf16.f32 "
        "{%0,%1,%2,%3}, {%4,%5,%6,%7}, {%8,%9}, {%0,%1,%2,%3};"
        : "+f"(c[0]), "+f"(c[1]), "+f"(c[2]), "+f"(c[3])
        : "r"(a[0]), "r"(a[1]), "r"(a[2]), "r"(a[3]), "r"(b[0]), "r"(b[1]));
}

#define LDSM4(r, addr)                                                        \
    asm volatile("ldmatrix.sync.aligned.m8n8.x4.shared.b16 "                  \
                 "{%0,%1,%2,%3}, [%4];"                                       \
                 : "=r"((r)[0]), "=r"((r)[1]), "=r"((r)[2]), "=r"((r)[3])     \
                 : "r"(addr))

#define S_XH 0
#define S_XL (S_XH + 128 * RSTRIDE)
#define S_WH (S_XL + 128 * RSTRIDE)
#define S_WL (S_WH + 128 * RSTRIDE)
#define S_TOTAL (S_WL + 128 * RSTRIDE)  // 139264
#define S_OUT 0

__device__ __forceinline__ void detect_stride(const int* __restrict__ ei32,
                                              int tid, int* s_st) {
    if (tid < 32) {
        int hi = __ldg(ei32 + 2 * tid + 1) | __ldg(ei32 + 2 * tid + 65);
        unsigned any = __ballot_sync(0xffffffffu, hi != 0);
        if (tid == 0) *s_st = any ? 1 : 2;
    }
    __syncthreads();
}

// ---------------------------------------------------------------------------
// CSR build (identical to the 120us version)
// ---------------------------------------------------------------------------
__global__ void k_count(const int* __restrict__ ei32, int E) {
    __shared__ int s_st;
    detect_stride(ei32, threadIdx.x, &s_st);
    int base = (blockIdx.x * blockDim.x + threadIdx.x) * 4;
    if (base >= E) return;
    int st = s_st;
    const int* dp = ei32 + (size_t)E * st;
    int d0 = __ldg(dp + (size_t)base * st);
    int d1 = (base + 1 < E) ? __ldg(dp + (size_t)(base + 1) * st) : -1;
    int d2 = (base + 2 < E) ? __ldg(dp + (size_t)(base + 2) * st) : -1;
    int d3 = (base + 3 < E) ? __ldg(dp + (size_t)(base + 3) * st) : -1;
    atomicAdd(&g_cnt[d0], 1);
    if (d1 >= 0) atomicAdd(&g_cnt[d1], 1);
    if (d2 >= 0) atomicAdd(&g_cnt[d2], 1);
    if (d3 >= 0) atomicAdd(&g_cnt[d3], 1);
}

__global__ void k_scan1(int Nn) {
    __shared__ int s_w[32], s_ws[32];
    int tidx = threadIdx.x, lane = tidx & 31, wid = tidx >> 5;
    int i = blockIdx.x * 1024 + tidx;
    int c = (i < Nn) ? g_cnt[i] : 0;
    int v = c;
#pragma unroll
    for (int o = 1; o < 32; o <<= 1) {
        int u = __shfl_up_sync(0xffffffffu, v, o);
        if (lane >= o) v += u;
    }
    if (lane == 31) s_w[wid] = v;
    __syncthreads();
    if (wid == 0) {
        int s = s_w[lane];
#pragma unroll
        for (int o = 1; o < 32; o <<= 1) {
            int u = __shfl_up_sync(0xffffffffu, s, o);
            if (lane >= o) s += u;
        }
        s_ws[lane] = s;
    }
    __syncthreads();
    int base = wid ? s_ws[wid - 1] : 0;
    int incl = base + v;
    g_off[i] = incl - c;
    if (tidx == 1023) g_bsum[blockIdx.x] = incl;
}

__global__ void k_scan23(int nb, int Nn) {
    __shared__ int s_b[128];
    int t = threadIdx.x;
    if (t < 128) s_b[t] = (t < nb) ? g_bsum[t] : 0;
    __syncthreads();
    for (int o = 1; o < 128; o <<= 1) {
        int v = 0;
        if (t < 128 && t >= o) v = s_b[t - o];
        __syncthreads();
        if (t < 128) s_b[t] += v;
        __syncthreads();
    }
    int boff = (blockIdx.x == 0) ? 0 : s_b[blockIdx.x - 1];
    int i = blockIdx.x * 1024 + t;
    if (i < Nn) {
        int o = g_off[i] + boff;
        g_off[i] = o;
        g_cur[i] = o;
        g_cnt[i] = 0;
    }
    if (blockIdx.x == 0 && t == 0) g_off[Nn] = s_b[nb - 1];
}

__global__ void k_fill(const int* __restrict__ ei32,
                       const float* __restrict__ ew, int E) {
    __shared__ int s_st;
    detect_stride(ei32, threadIdx.x, &s_st);
    int base = (blockIdx.x * blockDim.x + threadIdx.x) * 4;
    if (base >= E) return;
    int st = s_st;
    const int* sp = ei32;
    const int* dp = ei32 + (size_t)E * st;
    int s0, s1 = 0, s2 = 0, s3 = 0, d0, d1 = -1, d2 = -1, d3 = -1;
    float w0, w1 = 0.f, w2 = 0.f, w3 = 0.f;
    s0 = __ldg(sp + (size_t)base * st);
    d0 = __ldg(dp + (size_t)base * st);
    w0 = __ldg(ew + base);
    if (base + 1 < E) {
        s1 = __ldg(sp + (size_t)(base + 1) * st);
        d1 = __ldg(dp + (size_t)(base + 1) * st);
        w1 = __ldg(ew + base + 1);
    }
    if (base + 2 < E) {
        s2 = __ldg(sp + (size_t)(base + 2) * st);
        d2 = __ldg(dp + (size_t)(base + 2) * st);
        w2 = __ldg(ew + base + 2);
    }
    if (base + 3 < E) {
        s3 = __ldg(sp + (size_t)(base + 3) * st);
        d3 = __ldg(dp + (size_t)(base + 3) * st);
        w3 = __ldg(ew + base + 3);
    }
    g_sw[atomicAdd(&g_cur[d0], 1)] = make_int2(s0, __float_as_int(w0));
    if (d1 >= 0) g_sw[atomicAdd(&g_cur[d1], 1)] = make_int2(s1, __float_as_int(w1));
    if (d2 >= 0) g_sw[atomicAdd(&g_cur[d2], 1)] = make_int2(s2, __float_as_int(w2));
    if (d3 >= 0) g_sw[atomicAdd(&g_cur[d3], 1)] = make_int2(s3, __float_as_int(w3));
}

// ---------------------------------------------------------------------------
// GEMM helpers
// ---------------------------------------------------------------------------
__device__ __forceinline__ void load_split(const float* __restrict__ src,
                                           char* sm, int bh, int bl,
                                           int t, bool do_norm, float* xn2,
                                           int row0, int N) {
    int w = t >> 5, lane = t & 31;     // 16 warps: rows i*16 + w
#pragma unroll 4
    for (int i = 0; i < 8; i++) {
        int r = i * 16 + w;
        float4 v;
        if (do_norm) {
            int g = row0 + r;
            v = (g < N) ? *(const float4*)(src + (size_t)g * D + lane * 4)
                        : make_float4(0.f, 0.f, 0.f, 0.f);
            float s = wsum(v.x * v.x + v.y * v.y + v.z * v.z + v.w * v.w);
            if (lane == 0) xn2[r] = s;
        } else {
            v = *(const float4*)(src + (size_t)r * D + lane * 4);
        }
        __nv_bfloat162 h01 = __floats2bfloat162_rn(v.x, v.y);
        __nv_bfloat162 h23 = __floats2bfloat162_rn(v.z, v.w);
        float2 hf01 = __bfloat1622float2(h01);
        float2 hf23 = __bfloat1622float2(h23);
        __nv_bfloat162 l01 = __floats2bfloat162_rn(v.x - hf01.x, v.y - hf01.y);
        __nv_bfloat162 l23 = __floats2bfloat162_rn(v.z - hf23.x, v.w - hf23.y);
        uint2 hv = make_uint2(*(uint32_t*)&h01, *(uint32_t*)&h23);
        uint2 lv = make_uint2(*(uint32_t*)&l01, *(uint32_t*)&l23);
        int off = r * RSTRIDE + 8 * lane;
        *(uint2*)(sm + bh + off) = hv;
        *(uint2*)(sm + bl + off) = lv;
    }
}

__device__ __forceinline__ float2 mobius_ab(float mxn2, float mp, float xnn2,
                                            float y2) {
    float mxn_raw = sqrtf(mxn2);
    float mxn = fmaxf(mxn_raw, 1e-15f);
    float xn = fmaxf(sqrtf(xnn2), 1e-15f);
    float artx = atanhf(fminf(xn, 1.f - 1e-7f));
    float sc = tanhf(mxn / xn * artx) / mxn;
    if (mxn_raw <= 1e-10f) sc = 0.f;
    float x2 = sc * sc * mxn2;
    float xy = sc * mp;
    float c1 = 1.f + 2.f * xy + y2;
    float c2v = 1.f - x2;
    float den = fmaxf(1.f + 2.f * xy + x2 * y2, 1e-15f);
    float nb2 = (c1 * c1 * x2 + 2.f * c1 * c2v * xy + c2v * c2v * y2) /
                (den * den);
    float nb = fmaxf(sqrtf(nb2), 1e-15f);
    float sl = atanhf(fminf(nb, 1.f - 1e-7f)) / nb;
    return make_float2(sl * c1 * sc / den, sl * c2v / den);
}

// ---------------------------------------------------------------------------
// K1: persistent GEMM, 512 threads (16 warps), ldmatrix mainloop.
// Warp = (rowgroup wg, half h): rows 16*wg + g4 (+8), N-tiles [8h, 8h+8).
// ---------------------------------------------------------------------------
__global__ void __launch_bounds__(THREADS, 1)
k_linear(const float* __restrict__ x, const float* __restrict__ W,
         const float* __restrict__ b, int N, int ntiles) {
    extern __shared__ char sm[];
    __shared__ float xn2[128];
    __shared__ float p_s[128];
    __shared__ float red[4];
    __shared__ float s_p2;
    __shared__ float sA[THREADS], sB[THREADS], sC[THREADS], sD[THREADS];

    const int t = threadIdx.x;
    const int w = t >> 5, lane = t & 31;
    const int wg = w >> 1, half = w & 1;
    const int g4 = lane >> 2, tg = lane & 3;

    float bv = 0.f;
    if (t < 128) {
        bv = __ldg(b + t);
        float s = wsum(bv * bv);
        if ((t & 31) == 0) red[t >> 5] = s;
    }
    __syncthreads();
    float bn2 = red[0] + red[1] + red[2] + red[3];
    __syncthreads();
    if (t < 128) {
        float n = fmaxf(sqrtf(bn2), 1e-15f);
        float p = tanhf(n) * bv / n;
        p_s[t] = p;
        float s2 = wsum(p * p);
        if ((t & 31) == 0) red[t >> 5] = s2;
    }
    __syncthreads();
    if (t == 0) s_p2 = red[0] + red[1] + red[2] + red[3];

    load_split(W, sm, S_WH, S_WL, t, false, xn2, 0, N);   // resident

    const int r0 = 16 * wg + g4, r1 = r0 + 8;
    const int nt0 = 8 * half;               // first N-tile for this warp

    // per-lane ldmatrix base addresses (computed once)
    const uint32_t smb = smem_u32(sm);
    const uint32_t aoff = (uint32_t)((16 * wg + (lane & 15)) * RSTRIDE +
                                     (lane >> 4) * 16);
    const uint32_t aH = smb + S_XH + aoff;
    const uint32_t aL = smb + S_XL + aoff;
    uint32_t bH[4], bL[4];
#pragma unroll
    for (int p = 0; p < 4; p++) {
        uint32_t boff = (uint32_t)((8 * (nt0 + 2 * p) + (lane & 7) +
                                    (lane >> 4) * 8) * RSTRIDE +
                                   ((lane >> 3) & 1) * 16);
        bH[p] = smb + S_WH + boff;
        bL[p] = smb + S_WL + boff;
    }

    for (int tile = blockIdx.x; tile < ntiles; tile += gridDim.x) {
        const int row0 = tile * 128;
        load_split(x, sm, S_XH, S_XL, t, true, xn2, row0, N);
        __syncthreads();

        float acc[8][4];
#pragma unroll
        for (int nt = 0; nt < 8; nt++)
#pragma unroll
            for (int j = 0; j < 4; j++) acc[nt][j] = 0.f;

#pragma unroll
        for (int ks = 0; ks < 8; ks++) {
            const uint32_t ko = 32u * ks;
            uint32_t ah[4], al[4];
            LDSM4(ah, aH + ko);
            LDSM4(al, aL + ko);
#pragma unroll
            for (int p = 0; p < 4; p++) {
                uint32_t bh[4], bl[4];
                LDSM4(bh, bH[p] + ko);
                LDSM4(bl, bL[p] + ko);
                mma_bf16(acc[2 * p],     ah, bh);
                mma_bf16(acc[2 * p],     ah, bl);
                mma_bf16(acc[2 * p],     al, bh);
                mma_bf16(acc[2 * p + 1], ah, bh + 2);
                mma_bf16(acc[2 * p + 1], ah, bl + 2);
                mma_bf16(acc[2 * p + 1], al, bh + 2);
            }
        }

        // partial epilogue sums over this warp's 8 N-tiles (16 cols/row)
        float n2a = 0.f, mpa = 0.f, n2b = 0.f, mpb = 0.f;
#pragma unroll
        for (int nt = 0; nt < 8; nt++) {
            float p0 = p_s[8 * (nt0 + nt) + 2 * tg];
            float p1 = p_s[8 * (nt0 + nt) + 2 * tg + 1];
            n2a = fmaf(acc[nt][0], acc[nt][0], fmaf(acc[nt][1], acc[nt][1], n2a));
            mpa = fmaf(acc[nt][0], p0, fmaf(acc[nt][1], p1, mpa));
            n2b = fmaf(acc[nt][2], acc[nt][2], fmaf(acc[nt][3], acc[nt][3], n2b));
            mpb = fmaf(acc[nt][2], p0, fmaf(acc[nt][3], p1, mpb));
        }
        n2a += __shfl_xor_sync(0xffffffffu, n2a, 1);
        n2a += __shfl_xor_sync(0xffffffffu, n2a, 2);
        mpa += __shfl_xor_sync(0xffffffffu, mpa, 1);
        mpa += __shfl_xor_sync(0xffffffffu, mpa, 2);
        n2b += __shfl_xor_sync(0xffffffffu, n2b, 1);
        n2b += __shfl_xor_sync(0xffffffffu, n2b, 2);
        mpb += __shfl_xor_sync(0xffffffffu, mpb, 1);
        mpb += __shfl_xor_sync(0xffffffffu, mpb, 2);

        // cross-half combine (t ^ 32 = same wg/lane, other half)
        sA[t] = n2a; sB[t] = mpa; sC[t] = n2b; sD[t] = mpb;
        __syncthreads();
        n2a = sA[t] + sA[t ^ 32];
        mpa = sB[t] + sB[t ^ 32];
        n2b = sC[t] + sC[t ^ 32];
        mpb = sD[t] + sD[t ^ 32];

        const float y2 = s_p2;
        float2 ab0 = mobius_ab(n2a, mpa, xn2[r0], y2);
        float2 ab1 = mobius_ab(n2b, mpb, xn2[r1], y2);
        __syncthreads();   // sA..sD reads done; X region about to be staged

        float* stg = (float*)(sm + S_OUT);
#pragma unroll
        for (int nt = 0; nt < 8; nt++) {
            int c = 8 * (nt0 + nt) + 2 * tg;
            float p0 = p_s[c], p1 = p_s[c + 1];
            *(float2*)&stg[r0 * 132 + c] = make_float2(
                fmaf(ab0.x, acc[nt][0], ab0.y * p0),
                fmaf(ab0.x, acc[nt][1], ab0.y * p1));
            *(float2*)&stg[r1 * 132 + c] = make_float2(
                fmaf(ab1.x, acc[nt][2], ab1.y * p0),
                fmaf(ab1.x, acc[nt][3], ab1.y * p1));
        }
        __syncthreads();

        // coalesced flush: fp32 g_ht + fp16 mirror g_hth
#pragma unroll 2
        for (int idx = t; idx < 128 * 32; idx += THREADS) {
            int r2 = idx >> 5, c4 = idx & 31;
            int g = row0 + r2;
            if (g < N) {
                float4 v = *(const float4*)&stg[r2 * 132 + c4 * 4];
                *(float4*)&g_ht[(size_t)g * D + c4 * 4] = v;
                __half2 h01 = __floats2half2_rn(v.x, v.y);
                __half2 h23 = __floats2half2_rn(v.z, v.w);
                *(uint2*)(g_hth + (size_t)g * D + c4 * 4) =
                    make_uint2(*(uint32_t*)&h01, *(uint32_t*)&h23);
            }
        }
        __syncthreads();
    }
}

// ---------------------------------------------------------------------------
// K_agg: one warp per dst; batched meta prefetch + 4-way independent fp16
// gathers (uint2/lane); fp32 self; fused finalize.
// ---------------------------------------------------------------------------
__global__ void __launch_bounds__(256)
k_agg(float* __restrict__ out, const float* __restrict__ a_ptr, int N) {
    int gw = (int)((blockIdx.x * blockDim.x + threadIdx.x) >> 5);
    if (gw >= N) return;
    int lane = threadIdx.x & 31;
    float a = __ldg(a_ptr);

    int beg = g_off[gw], end = g_off[gw + 1];
    int deg = end - beg;
    float4 acc = __ldg((const float4*)(g_ht + (size_t)gw * D) + lane);

    for (int base = 0; base < deg; base += 32) {
        int m = deg - base; if (m > 32) m = 32;
        int2 meta = make_int2(0, 0);      // src 0 weight +0 = exact no-op
        if (lane < m) meta = __ldg(&g_sw[beg + base + lane]);
        for (int j = 0; j < m; j += 4) {
            int s0 = __shfl_sync(0xffffffffu, meta.x, j);
            int s1 = __shfl_sync(0xffffffffu, meta.x, j + 1);
            int s2 = __shfl_sync(0xffffffffu, meta.x, j + 2);
            int s3 = __shfl_sync(0xffffffffu, meta.x, j + 3);
            float w0 = __int_as_float(__shfl_sync(0xffffffffu, meta.y, j));
            float w1 = __int_as_float(__shfl_sync(0xffffffffu, meta.y, j + 1));
            float w2 = __int_as_float(__shfl_sync(0xffffffffu, meta.y, j + 2));
            float w3 = __int_as_float(__shfl_sync(0xffffffffu, meta.y, j + 3));
            uint2 u0 = __ldg((const uint2*)(g_hth + (size_t)s0 * D) + lane);
            uint2 u1 = __ldg((const uint2*)(g_hth + (size_t)s1 * D) + lane);
            uint2 u2 = __ldg((const uint2*)(g_hth + (size_t)s2 * D) + lane);
            uint2 u3 = __ldg((const uint2*)(g_hth + (size_t)s3 * D) + lane);
            float2 l0 = __half22float2(*(__half2*)&u0.x);
            float2 h0 = __half22float2(*(__half2*)&u0.y);
            float2 l1 = __half22float2(*(__half2*)&u1.x);
            float2 h1 = __half22float2(*(__half2*)&u1.y);
            float2 l2 = __half22float2(*(__half2*)&u2.x);
            float2 h2 = __half22float2(*(__half2*)&u2.y);
            float2 l3 = __half22float2(*(__half2*)&u3.x);
            float2 h3 = __half22float2(*(__half2*)&u3.y);
            acc.x = fmaf(w0, l0.x, fmaf(w1, l1.x, fmaf(w2, l2.x, fmaf(w3, l3.x, acc.x))));
            acc.y = fmaf(w0, l0.y, fmaf(w1, l1.y, fmaf(w2, l2.y, fmaf(w3, l3.y, acc.y))));
            acc.z = fmaf(w0, h0.x, fmaf(w1, h1.x, fmaf(w2, h2.x, fmaf(w3, h3.x, acc.z))));
            acc.w = fmaf(w0, h0.y, fmaf(w1, h1.y, fmaf(w2, h2.y, fmaf(w3, h3.y, acc.w))));
        }
    }

    float n1 = fmaxf(sqrtf(wsum(acc.x * acc.x + acc.y * acc.y +
                                acc.z * acc.z + acc.w * acc.w)), 1e-15f);
    float s = atanhf(fminf(tanhf(n1), 1.f - 1e-7f)) / n1;
    float tx = acc.x * s, ty = acc.y * s, tz = acc.z * s, tw = acc.w * s;
    tx = tx >= 0.f ? tx : a * tx;
    ty = ty >= 0.f ? ty : a * ty;
    tz = tz >= 0.f ? tz : a * tz;
    tw = tw >= 0.f ? tw : a * tw;
    float n3 = fmaxf(sqrtf(wsum(tx * tx + ty * ty + tz * tz + tw * tw)), 1e-15f);
    float th = tanhf(n3);
    float s2 = th / n3;
    float ox = tx * s2, oy = ty * s2, oz = tz * s2, ow = tw * s2;
    float n4 = fmaxf(th, 1e-15f);
    const float maxn = 1.f - 4e-3f;
    if (n4 > maxn) {
        float f = maxn / n4;
        ox *= f; oy *= f; oz *= f; ow *= f;
    }
    *((float4*)(out + (size_t)gw * D) + lane) = make_float4(ox, oy, oz, ow);
}

// ---------------------------------------------------------------------------
extern "C" void kernel_launch(void* const* d_in, const int* in_sizes, int n_in,
                              void* d_out, int out_size) {
    const float* x    = (const float*)d_in[0];
    const int*   ei32 = (const int*)d_in[1];
    const float* ew   = (const float*)d_in[2];
    const float* W    = (const float*)d_in[3];
    const float* b    = (const float*)d_in[4];
    const float* a    = (const float*)d_in[5];
    float* out = (float*)d_out;

    int N = in_sizes[0] / D;
    int E = in_sizes[2];
    int nb = (N + 1023) / 1024;
    int ntiles = (N + 127) / 128;
    int e4 = (E + 1023) / 1024;

    // fork: full CSR build on side stream BEFORE k_linear (proven order)
    cudaEventRecord(g_hx.eF, 0);
    cudaStreamWaitEvent(g_hx.s2, g_hx.eF, 0);
    k_count<<<e4, 256, 0, g_hx.s2>>>(ei32, E);
    k_scan1<<<nb, 1024, 0, g_hx.s2>>>(N);
    k_scan23<<<nb, 1024, 0, g_hx.s2>>>(nb, N);
    k_fill<<<e4, 256, 0, g_hx.s2>>>(ei32, ew, E);
    cudaEventRecord(g_hx.eJ, g_hx.s2);

    cudaFuncSetAttribute(k_linear, cudaFuncAttributeMaxDynamicSharedMemorySize,
                         S_TOTAL);
    int grid = ntiles < 148 ? ntiles : 148;
    k_linear<<<grid, THREADS, S_TOTAL>>>(x, W, b, N, ntiles);

    cudaStreamWaitEvent(0, g_hx.eJ, 0);
    k_agg<<<(N * 32 + 255) / 256, 256>>>(out, a, N);
}